// round 4
// baseline (speedup 1.0000x reference)
#include <cuda_runtime.h>
#include <cuda_bf16.h>
#include <cstdint>

// Problem constants (fixed by the dataset)
#define BS 8
#define NQ 2048
#define MP 64
#define DD 1024

// Tiling
#define KC 32                   // K-chunk (d elems) per stage
#define KSPLIT 2                // split-K factor
#define KPER (DD / KSPLIT)      // 512 d-elems per CTA
#define NCHUNKS (KPER / KC)     // 16 chunks per CTA
#define ASTRIDE 40              // KC + 8 pad (bf16) -> conflict-free LDS.32
#define NROWS 64                // CTA rows (N tile)
#define NTHREADS 128            // 4 warps (2x2), warp tile 32x32

#define OUTELEMS (BS * NQ * MP) // 1,048,576

// __device__ scratch (allocation-free rule)
__device__ __nv_bfloat16 g_B1[BS * MP * DD];        // mask^2
__device__ __nv_bfloat16 g_B2[BS * MP * DD];        // -2 * mask^2 * p
__device__ float         g_pterm[BS * MP];          // sum_d (mask*p)^2
__device__ float         g_part[KSPLIT][OUTELEMS];  // split-K partials (8 MB)

// ---------------------------------------------------------------------------
// Prep kernel: build bf16 B matrices + pterm.
// ---------------------------------------------------------------------------
__global__ void proto_prep_kernel(const float* __restrict__ proto,
                                  const float* __restrict__ mask) {
    const int bm = blockIdx.x;
    const int t  = threadIdx.x;
    const float* mrow = mask  + (size_t)bm * DD;
    const float* prow = proto + (size_t)bm * DD;

    float psum = 0.f;
    #pragma unroll 2
    for (int d = t; d < DD; d += 256) {
        float mk = mrow[d];
        float p  = prow[d];
        float m2 = mk * mk;
        g_B1[(size_t)bm * DD + d] = __float2bfloat16(m2);
        g_B2[(size_t)bm * DD + d] = __float2bfloat16(-2.0f * m2 * p);
        float mp = mk * p;
        psum += mp * mp;
    }
    __shared__ float red[256];
    red[t] = psum;
    __syncthreads();
    #pragma unroll
    for (int s = 128; s > 0; s >>= 1) {
        if (t < s) red[t] += red[t + s];
        __syncthreads();
    }
    if (t == 0) g_pterm[bm] = red[0];
}

// ---------------------------------------------------------------------------
// Helpers
// ---------------------------------------------------------------------------
__device__ __forceinline__ void cp_async16(void* smem_dst, const void* gmem_src) {
    uint32_t s = (uint32_t)__cvta_generic_to_shared(smem_dst);
    asm volatile("cp.async.cg.shared.global [%0], [%1], 16;\n" :: "r"(s), "l"(gmem_src));
}
__device__ __forceinline__ uint32_t sq_bf16x2(uint32_t x) {
    __nv_bfloat162 v = *reinterpret_cast<__nv_bfloat162*>(&x);
    __nv_bfloat162 r = __hmul2(v, v);
    return *reinterpret_cast<uint32_t*>(&r);
}

// ---------------------------------------------------------------------------
// Main kernel: pipelined fused dual-GEMM, split-K.
// grid = (NQ/64, BS, KSPLIT) = (32, 8, 2) = 512 CTAs; block = 128 (4 warps).
// Each CTA accumulates over 512 d-elems and writes a raw partial (no pterm,
// no scale) to g_part[blockIdx.z].
// ---------------------------------------------------------------------------
__global__ __launch_bounds__(NTHREADS, 4)
void proto_logits_kernel(const float* __restrict__ q) {
    __shared__ __align__(16) __nv_bfloat16 sQ [2][NROWS * ASTRIDE];
    __shared__ __align__(16) __nv_bfloat16 sB1[2][MP * ASTRIDE];
    __shared__ __align__(16) __nv_bfloat16 sB2[2][MP * ASTRIDE];

    const int b    = blockIdx.y;
    const int n0   = blockIdx.x * NROWS;
    const int kofs = blockIdx.z * KPER;
    const int t    = threadIdx.x;
    const int warp = t >> 5;
    const int lane = t & 31;
    const int wm   = warp >> 1;
    const int wn   = warp & 1;
    const int gid  = lane >> 2;
    const int tig  = lane & 3;

    float acc[2][4][4];
    #pragma unroll
    for (int i = 0; i < 2; i++)
        #pragma unroll
        for (int j = 0; j < 4; j++)
            #pragma unroll
            for (int k = 0; k < 4; k++) acc[i][j][k] = 0.f;

    const float*         qbase  = q    + ((size_t)b * NQ + n0) * DD + kofs;
    const __nv_bfloat16* B1base = g_B1 + (size_t)b * MP * DD + kofs;
    const __nv_bfloat16* B2base = g_B2 + (size_t)b * MP * DD + kofs;

    const int q_row0 = t >> 3;          // rows: q_row0 + 16*j
    const int q_c4   = t & 7;
    const int b_row0 = t >> 2;          // 0..31; second op at +32
    const int b_c16  = t & 3;

    float4 qr[4];

    // ---- prologue
    {
        #pragma unroll
        for (int h = 0; h < 2; h++) {
            int row = b_row0 + 32 * h;
            const __nv_bfloat16* s1 = B1base + (size_t)row * DD + b_c16 * 8;
            const __nv_bfloat16* s2 = B2base + (size_t)row * DD + b_c16 * 8;
            cp_async16(&sB1[0][row * ASTRIDE + b_c16 * 8], s1);
            cp_async16(&sB2[0][row * ASTRIDE + b_c16 * 8], s2);
        }
        asm volatile("cp.async.commit_group;\n");
        #pragma unroll
        for (int j = 0; j < 4; j++)
            qr[j] = *(const float4*)(qbase + (size_t)(q_row0 + 16 * j) * DD + q_c4 * 4);
    }

    for (int i = 0; i < NCHUNKS; ++i) {
        const int buf = i & 1;

        #pragma unroll
        for (int j = 0; j < 4; j++) {
            int so = (q_row0 + 16 * j) * ASTRIDE + q_c4 * 4;
            __nv_bfloat162 lo = __floats2bfloat162_rn(qr[j].x, qr[j].y);
            __nv_bfloat162 hi = __floats2bfloat162_rn(qr[j].z, qr[j].w);
            *(uint32_t*)(&sQ[buf][so + 0]) = *reinterpret_cast<uint32_t*>(&lo);
            *(uint32_t*)(&sQ[buf][so + 2]) = *reinterpret_cast<uint32_t*>(&hi);
        }
        asm volatile("cp.async.wait_group 0;\n");
        __syncthreads();

        if (i + 1 < NCHUNKS) {
            const int d1 = (i + 1) * KC;
            #pragma unroll
            for (int h = 0; h < 2; h++) {
                int row = b_row0 + 32 * h;
                const __nv_bfloat16* s1 = B1base + (size_t)row * DD + d1 + b_c16 * 8;
                const __nv_bfloat16* s2 = B2base + (size_t)row * DD + d1 + b_c16 * 8;
                cp_async16(&sB1[buf ^ 1][row * ASTRIDE + b_c16 * 8], s1);
                cp_async16(&sB2[buf ^ 1][row * ASTRIDE + b_c16 * 8], s2);
            }
            asm volatile("cp.async.commit_group;\n");
            #pragma unroll
            for (int j = 0; j < 4; j++)
                qr[j] = *(const float4*)(qbase + (size_t)(q_row0 + 16 * j) * DD + d1 + q_c4 * 4);
        }

        #pragma unroll
        for (int kk = 0; kk < KC; kk += 16) {
            uint32_t aq[2][4], aq2[2][4];
            #pragma unroll
            for (int mt = 0; mt < 2; mt++) {
                int r = wm * 32 + mt * 16 + gid;
                const __nv_bfloat16* base = &sQ[buf][r * ASTRIDE + kk + tig * 2];
                aq[mt][0] = *(const uint32_t*)(base);
                aq[mt][1] = *(const uint32_t*)(base + 8 * ASTRIDE);
                aq[mt][2] = *(const uint32_t*)(base + 8);
                aq[mt][3] = *(const uint32_t*)(base + 8 * ASTRIDE + 8);
                #pragma unroll
                for (int r4 = 0; r4 < 4; r4++) aq2[mt][r4] = sq_bf16x2(aq[mt][r4]);
            }
            uint32_t b1f[4][2], b2f[4][2];
            #pragma unroll
            for (int nt = 0; nt < 4; nt++) {
                int nn = wn * 32 + nt * 8 + gid;
                const __nv_bfloat16* p1 = &sB1[buf][nn * ASTRIDE + kk + tig * 2];
                const __nv_bfloat16* p2 = &sB2[buf][nn * ASTRIDE + kk + tig * 2];
                b1f[nt][0] = *(const uint32_t*)(p1);
                b1f[nt][1] = *(const uint32_t*)(p1 + 8);
                b2f[nt][0] = *(const uint32_t*)(p2);
                b2f[nt][1] = *(const uint32_t*)(p2 + 8);
            }
            #pragma unroll
            for (int mt = 0; mt < 2; mt++)
                #pragma unroll
                for (int nt = 0; nt < 4; nt++) {
                    asm volatile(
                        "mma.sync.aligned.m16n8k16.row.col.f32.bf16.bf16.f32 "
                        "{%0,%1,%2,%3}, {%4,%5,%6,%7}, {%8,%9}, {%0,%1,%2,%3};\n"
                        : "+f"(acc[mt][nt][0]), "+f"(acc[mt][nt][1]),
                          "+f"(acc[mt][nt][2]), "+f"(acc[mt][nt][3])
                        : "r"(aq2[mt][0]), "r"(aq2[mt][1]),
                          "r"(aq2[mt][2]), "r"(aq2[mt][3]),
                          "r"(b1f[nt][0]), "r"(b1f[nt][1]));
                    asm volatile(
                        "mma.sync.aligned.m16n8k16.row.col.f32.bf16.bf16.f32 "
                        "{%0,%1,%2,%3}, {%4,%5,%6,%7}, {%8,%9}, {%0,%1,%2,%3};\n"
                        : "+f"(acc[mt][nt][0]), "+f"(acc[mt][nt][1]),
                          "+f"(acc[mt][nt][2]), "+f"(acc[mt][nt][3])
                        : "r"(aq[mt][0]), "r"(aq[mt][1]),
                          "r"(aq[mt][2]), "r"(aq[mt][3]),
                          "r"(b2f[nt][0]), "r"(b2f[nt][1]));
                }
        }
    }

    // ---- epilogue: write raw partial sums
    float* pbase = &g_part[blockIdx.z][((size_t)b * NQ + n0) * MP];
    #pragma unroll
    for (int mt = 0; mt < 2; mt++) {
        #pragma unroll
        for (int nt = 0; nt < 4; nt++) {
            int r0 = wm * 32 + mt * 16 + gid;
            int c0 = wn * 32 + nt * 8 + tig * 2;
            float2 o01 = make_float2(acc[mt][nt][0], acc[mt][nt][1]);
            float2 o23 = make_float2(acc[mt][nt][2], acc[mt][nt][3]);
            *(float2*)(pbase + (size_t)r0 * MP + c0)       = o01;
            *(float2*)(pbase + (size_t)(r0 + 8) * MP + c0) = o23;
        }
    }
}

// ---------------------------------------------------------------------------
// Reduce: out = scale/D * (p0 + p1 + pterm[b,m]). One float4 per thread.
// grid = OUTELEMS/4/256 = 1024 blocks.
// ---------------------------------------------------------------------------
__global__ __launch_bounds__(256, 8)
void proto_reduce_kernel(const float* __restrict__ scale,
                         float* __restrict__ out) {
    const int idx = blockIdx.x * 256 + threadIdx.x;   // float4 index
    const float s = scale[0] * (1.0f / (float)DD);

    float4 a = *((const float4*)g_part[0] + idx);
    float4 c = *((const float4*)g_part[1] + idx);

    const int e0 = idx * 4;
    const int bm = ((e0 / (NQ * MP)) * MP) + (e0 & (MP - 1)); // b*MP + m0
    float4 p = *(const float4*)(g_pterm + bm);

    float4 o;
    o.x = s * (a.x + c.x + p.x);
    o.y = s * (a.y + c.y + p.y);
    o.z = s * (a.z + c.z + p.z);
    o.w = s * (a.w + c.w + p.w);
    *((float4*)out + idx) = o;
}

// ---------------------------------------------------------------------------
// Launch. Inputs: 0=prototypes, 1=masktypes, 2=query, 3=support,
// 4=support_labels, 5=scale. Output: [8,2048,64] f32.
// ---------------------------------------------------------------------------
extern "C" void kernel_launch(void* const* d_in, const int* in_sizes, int n_in,
                              void* d_out, int out_size) {
    const float* proto = (const float*)d_in[0];
    const float* mask  = (const float*)d_in[1];
    const float* query = (const float*)d_in[2];
    const float* scale = (const float*)d_in[5];
    float* out = (float*)d_out;

    proto_prep_kernel<<<BS * MP, 256>>>(proto, mask);
    dim3 grid(NQ / NROWS, BS, KSPLIT);
    proto_logits_kernel<<<grid, NTHREADS>>>(query);
    proto_reduce_kernel<<<OUTELEMS / 4 / 256, 256>>>(scale, out);
}

// round 6
// speedup vs baseline: 1.8734x; 1.8734x over previous
#include <cuda_runtime.h>
#include <cuda_bf16.h>
#include <cstdint>

// Problem constants (fixed by the dataset)
#define BS 8
#define NQ 2048
#define MP 64
#define DD 1024

// Tiling
#define KC 64                  // K-chunk (d elems) per stage
#define NCHUNKS (DD / KC)      // 16
#define ASTRIDE 72             // KC + 8 pad (bf16 elems) -> conflict-free LDS.32
#define NROWS 128              // CTA rows (N tile)
#define NTHREADS 256           // 8 warps (4x2), warp tile 32x32

// Dynamic smem: per stage [q: 128*72][b1: 64*72][b2: 64*72] bf16 elems
#define QELEMS   (NROWS * ASTRIDE)          // 9216
#define BELEMS   (MP * ASTRIDE)             // 4608
#define STAGEELE (QELEMS + 2 * BELEMS)      // 18432 elems = 36864 B
#define SMEM_TOTAL (2 * STAGEELE * 2)       // 73728 B

// __device__ scratch (allocation-free rule)
__device__ __nv_bfloat16 g_B1[BS * MP * DD];   // mask^2
__device__ __nv_bfloat16 g_B2[BS * MP * DD];   // -2 * mask^2 * p
__device__ float         g_pterm[BS * MP];     // sum_d (mask*p)^2

// ---------------------------------------------------------------------------
// Prep: vectorized, one float4 per thread. grid = BS*MP = 512, block = 256.
// ---------------------------------------------------------------------------
__global__ __launch_bounds__(256, 4)
void proto_prep_kernel(const float* __restrict__ proto,
                       const float* __restrict__ mask) {
    const int bm = blockIdx.x;
    const int t  = threadIdx.x;
    float4 mk = ((const float4*)(mask  + (size_t)bm * DD))[t];
    float4 p  = ((const float4*)(proto + (size_t)bm * DD))[t];

    float4 m2 = make_float4(mk.x * mk.x, mk.y * mk.y, mk.z * mk.z, mk.w * mk.w);
    float4 b2 = make_float4(-2.f * m2.x * p.x, -2.f * m2.y * p.y,
                            -2.f * m2.z * p.z, -2.f * m2.w * p.w);

    __nv_bfloat162 a01 = __floats2bfloat162_rn(m2.x, m2.y);
    __nv_bfloat162 a23 = __floats2bfloat162_rn(m2.z, m2.w);
    __nv_bfloat162 c01 = __floats2bfloat162_rn(b2.x, b2.y);
    __nv_bfloat162 c23 = __floats2bfloat162_rn(b2.z, b2.w);
    uint2 u1 = make_uint2(*(uint32_t*)&a01, *(uint32_t*)&a23);
    uint2 u2 = make_uint2(*(uint32_t*)&c01, *(uint32_t*)&c23);
    *(uint2*)(g_B1 + (size_t)bm * DD + t * 4) = u1;
    *(uint2*)(g_B2 + (size_t)bm * DD + t * 4) = u2;

    float mpx = mk.x * p.x, mpy = mk.y * p.y, mpz = mk.z * p.z, mpw = mk.w * p.w;
    float psum = mpx * mpx + mpy * mpy + mpz * mpz + mpw * mpw;

    __shared__ float red[256];
    red[t] = psum;
    __syncthreads();
    #pragma unroll
    for (int s = 128; s > 0; s >>= 1) {
        if (t < s) red[t] += red[t + s];
        __syncthreads();
    }
    if (t == 0) g_pterm[bm] = red[0];
}

// ---------------------------------------------------------------------------
// Helpers
// ---------------------------------------------------------------------------
__device__ __forceinline__ void cp_async16(void* smem_dst, const void* gmem_src) {
    uint32_t s = (uint32_t)__cvta_generic_to_shared(smem_dst);
    asm volatile("cp.async.cg.shared.global [%0], [%1], 16;\n" :: "r"(s), "l"(gmem_src));
}
__device__ __forceinline__ uint32_t sq_bf16x2(uint32_t x) {
    __nv_bfloat162 v = *reinterpret_cast<__nv_bfloat162*>(&x);
    __nv_bfloat162 r = __hmul2(v, v);
    return *reinterpret_cast<uint32_t*>(&r);
}

// ---------------------------------------------------------------------------
// Main kernel: pipelined fused dual-GEMM, KC=64.
// grid = (16, 8) = 128 CTAs; block = 256 (8 warps, 4x2), warp tile 32x32.
// ---------------------------------------------------------------------------
__global__ __launch_bounds__(NTHREADS, 1)
void proto_logits_kernel(const float* __restrict__ q,
                         const float* __restrict__ scale,
                         float* __restrict__ out) {
    extern __shared__ __align__(16) __nv_bfloat16 smem[];
    // stage s: q at s*STAGEELE, B1 at +QELEMS, B2 at +QELEMS+BELEMS

    const int b    = blockIdx.y;
    const int n0   = blockIdx.x * NROWS;
    const int t    = threadIdx.x;
    const int warp = t >> 5;
    const int lane = t & 31;
    const int wm   = warp >> 1;     // 0..3
    const int wn   = warp & 1;      // 0..1
    const int gid  = lane >> 2;
    const int tig  = lane & 3;

    float acc[2][4][4];
    #pragma unroll
    for (int i = 0; i < 2; i++)
        #pragma unroll
        for (int j = 0; j < 4; j++)
            #pragma unroll
            for (int k = 0; k < 4; k++) acc[i][j][k] = 0.f;

    const float*         qbase  = q    + ((size_t)b * NQ + n0) * DD;
    const __nv_bfloat16* B1base = g_B1 + (size_t)b * MP * DD;
    const __nv_bfloat16* B2base = g_B2 + (size_t)b * MP * DD;

    // q staging: 128 rows x 64 floats = 2048 float4; 8 per thread.
    // gidx = t + 256*p -> row = gidx>>4, g = gidx&15 (float4 group)
    const int q_row0 = t >> 4;          // rows: q_row0 + 16*p
    const int q_g    = t & 15;

    // B staging: 2 matrices x 64 rows x 8 (16B groups) = 1024 cp.async; 4/thread
    // idx = t + 256*h -> mat = idx>>9, row = (idx>>3)&63, g = idx&7
    float4 qr[8];

    // ---- prologue: issue B_0 cp.async, LDG q_0
    {
        #pragma unroll
        for (int h = 0; h < 4; h++) {
            int idx = t + 256 * h;
            int mat = idx >> 9;
            int row = (idx >> 3) & 63;
            int g   = idx & 7;
            const __nv_bfloat16* src =
                (mat ? B2base : B1base) + (size_t)row * DD + g * 8;
            __nv_bfloat16* dst = smem + QELEMS + mat * BELEMS + row * ASTRIDE + g * 8;
            cp_async16(dst, src);
        }
        asm volatile("cp.async.commit_group;\n");
        #pragma unroll
        for (int p = 0; p < 8; p++)
            qr[p] = *(const float4*)(qbase + (size_t)(q_row0 + 16 * p) * DD + q_g * 4);
    }

    for (int i = 0; i < NCHUNKS; ++i) {
        const int buf = i & 1;
        __nv_bfloat16* sQ  = smem + buf * STAGEELE;
        __nv_bfloat16* sB1 = sQ + QELEMS;
        __nv_bfloat16* sB2 = sB1 + BELEMS;

        // store q_i (fp32 regs -> bf16 smem)
        #pragma unroll
        for (int p = 0; p < 8; p++) {
            int so = (q_row0 + 16 * p) * ASTRIDE + q_g * 4;
            __nv_bfloat162 lo = __floats2bfloat162_rn(qr[p].x, qr[p].y);
            __nv_bfloat162 hi = __floats2bfloat162_rn(qr[p].z, qr[p].w);
            uint2 v = make_uint2(*(uint32_t*)&lo, *(uint32_t*)&hi);
            *(uint2*)(&sQ[so]) = v;
        }
        asm volatile("cp.async.wait_group 0;\n");
        __syncthreads();

        // issue next-stage loads (overlap with compute below)
        if (i + 1 < NCHUNKS) {
            const int d1 = (i + 1) * KC;
            __nv_bfloat16* nQ  = smem + (buf ^ 1) * STAGEELE;
            __nv_bfloat16* nB1 = nQ + QELEMS;
            #pragma unroll
            for (int h = 0; h < 4; h++) {
                int idx = t + 256 * h;
                int mat = idx >> 9;
                int row = (idx >> 3) & 63;
                int g   = idx & 7;
                const __nv_bfloat16* src =
                    (mat ? B2base : B1base) + (size_t)row * DD + d1 + g * 8;
                __nv_bfloat16* dst = nB1 + mat * BELEMS + row * ASTRIDE + g * 8;
                cp_async16(dst, src);
            }
            asm volatile("cp.async.commit_group;\n");
            #pragma unroll
            for (int p = 0; p < 8; p++)
                qr[p] = *(const float4*)(qbase + (size_t)(q_row0 + 16 * p) * DD + d1 + q_g * 4);
        }

        // compute chunk i: 4 k-steps of 16
        #pragma unroll
        for (int kk = 0; kk < KC; kk += 16) {
            uint32_t aq[2][4], aq2[2][4];
            #pragma unroll
            for (int mt = 0; mt < 2; mt++) {
                int r = wm * 32 + mt * 16 + gid;
                const __nv_bfloat16* base = &sQ[r * ASTRIDE + kk + tig * 2];
                aq[mt][0] = *(const uint32_t*)(base);
                aq[mt][1] = *(const uint32_t*)(base + 8 * ASTRIDE);
                aq[mt][2] = *(const uint32_t*)(base + 8);
                aq[mt][3] = *(const uint32_t*)(base + 8 * ASTRIDE + 8);
                #pragma unroll
                for (int r4 = 0; r4 < 4; r4++) aq2[mt][r4] = sq_bf16x2(aq[mt][r4]);
            }
            uint32_t b1f[4][2], b2f[4][2];
            #pragma unroll
            for (int nt = 0; nt < 4; nt++) {
                int nn = wn * 32 + nt * 8 + gid;
                const __nv_bfloat16* p1 = &sB1[nn * ASTRIDE + kk + tig * 2];
                const __nv_bfloat16* p2 = &sB2[nn * ASTRIDE + kk + tig * 2];
                b1f[nt][0] = *(const uint32_t*)(p1);
                b1f[nt][1] = *(const uint32_t*)(p1 + 8);
                b2f[nt][0] = *(const uint32_t*)(p2);
                b2f[nt][1] = *(const uint32_t*)(p2 + 8);
            }
            #pragma unroll
            for (int mt = 0; mt < 2; mt++)
                #pragma unroll
                for (int nt = 0; nt < 4; nt++) {
                    asm volatile(
                        "mma.sync.aligned.m16n8k16.row.col.f32.bf16.bf16.f32 "
                        "{%0,%1,%2,%3}, {%4,%5,%6,%7}, {%8,%9}, {%0,%1,%2,%3};\n"
                        : "+f"(acc[mt][nt][0]), "+f"(acc[mt][nt][1]),
                          "+f"(acc[mt][nt][2]), "+f"(acc[mt][nt][3])
                        : "r"(aq2[mt][0]), "r"(aq2[mt][1]),
                          "r"(aq2[mt][2]), "r"(aq2[mt][3]),
                          "r"(b1f[nt][0]), "r"(b1f[nt][1]));
                    asm volatile(
                        "mma.sync.aligned.m16n8k16.row.col.f32.bf16.bf16.f32 "
                        "{%0,%1,%2,%3}, {%4,%5,%6,%7}, {%8,%9}, {%0,%1,%2,%3};\n"
                        : "+f"(acc[mt][nt][0]), "+f"(acc[mt][nt][1]),
                          "+f"(acc[mt][nt][2]), "+f"(acc[mt][nt][3])
                        : "r"(aq[mt][0]), "r"(aq[mt][1]),
                          "r"(aq[mt][2]), "r"(aq[mt][3]),
                          "r"(b2f[nt][0]), "r"(b2f[nt][1]));
                }
        }
        if (i + 1 < NCHUNKS) __syncthreads();
    }

    // ---- epilogue: out = scale/D * (acc + pterm[col])
    const float s = scale[0] * (1.0f / (float)DD);
    float* obase = out + ((size_t)b * NQ + n0) * MP;
    const float* pt = g_pterm + b * MP;
    #pragma unroll
    for (int mt = 0; mt < 2; mt++) {
        #pragma unroll
        for (int nt = 0; nt < 4; nt++) {
            int r0 = wm * 32 + mt * 16 + gid;
            int c0 = wn * 32 + nt * 8 + tig * 2;
            float p0 = pt[c0];
            float p1 = pt[c0 + 1];
            float2 o01 = make_float2(s * (acc[mt][nt][0] + p0),
                                     s * (acc[mt][nt][1] + p1));
            float2 o23 = make_float2(s * (acc[mt][nt][2] + p0),
                                     s * (acc[mt][nt][3] + p1));
            *(float2*)(obase + (size_t)r0 * MP + c0)       = o01;
            *(float2*)(obase + (size_t)(r0 + 8) * MP + c0) = o23;
        }
    }
}

// ---------------------------------------------------------------------------
// Launch. Inputs: 0=prototypes, 1=masktypes, 2=query, 3=support,
// 4=support_labels, 5=scale. Output: [8,2048,64] f32.
// ---------------------------------------------------------------------------
extern "C" void kernel_launch(void* const* d_in, const int* in_sizes, int n_in,
                              void* d_out, int out_size) {
    const float* proto = (const float*)d_in[0];
    const float* mask  = (const float*)d_in[1];
    const float* query = (const float*)d_in[2];
    const float* scale = (const float*)d_in[5];
    float* out = (float*)d_out;

    cudaFuncSetAttribute(proto_logits_kernel,
                         cudaFuncAttributeMaxDynamicSharedMemorySize, SMEM_TOTAL);

    proto_prep_kernel<<<BS * MP, 256>>>(proto, mask);
    dim3 grid(NQ / NROWS, BS);
    proto_logits_kernel<<<grid, NTHREADS, SMEM_TOTAL>>>(query, scale, out);
}

// round 7
// speedup vs baseline: 1.9069x; 1.0179x over previous
#include <cuda_runtime.h>
#include <cuda_bf16.h>
#include <cstdint>

// Problem constants (fixed by the dataset)
#define BS 8
#define NQ 2048
#define MP 64
#define DD 1024

// Tiling
#define KC 64                  // K-chunk (d elems) per stage
#define NCHUNKS (DD / KC)      // 16
#define ASTRIDE 72             // KC + 8 pad (bf16 elems) -> conflict-free LDS.32
#define NROWS 128              // CTA rows (N tile)
#define NTHREADS 256           // 8 warps (4x2), warp tile 32x32

// Smem layout (bf16 elems): q double-buffered, B 4-stage ring
#define QELEMS   (NROWS * ASTRIDE)              // 9216
#define BELEMS   (MP * ASTRIDE)                 // 4608
#define BSTAGE   (2 * BELEMS)                   // B1+B2 per stage
#define BBASE    (2 * QELEMS)
#define SMEM_TOTAL ((2 * QELEMS + 4 * BSTAGE) * 2)   // 110592 B

// __device__ scratch (allocation-free rule)
__device__ __nv_bfloat16 g_B1[BS * MP * DD];   // mask^2
__device__ __nv_bfloat16 g_B2[BS * MP * DD];   // -2 * mask^2 * p
__device__ float         g_pterm[BS * MP];     // sum_d (mask*p)^2

// ---------------------------------------------------------------------------
// Prep: vectorized, one float4 per thread. grid = BS*MP = 512, block = 256.
// ---------------------------------------------------------------------------
__global__ __launch_bounds__(256, 4)
void proto_prep_kernel(const float* __restrict__ proto,
                       const float* __restrict__ mask) {
    const int bm = blockIdx.x;
    const int t  = threadIdx.x;
    float4 mk = ((const float4*)(mask  + (size_t)bm * DD))[t];
    float4 p  = ((const float4*)(proto + (size_t)bm * DD))[t];

    float4 m2 = make_float4(mk.x * mk.x, mk.y * mk.y, mk.z * mk.z, mk.w * mk.w);
    float4 b2 = make_float4(-2.f * m2.x * p.x, -2.f * m2.y * p.y,
                            -2.f * m2.z * p.z, -2.f * m2.w * p.w);

    __nv_bfloat162 a01 = __floats2bfloat162_rn(m2.x, m2.y);
    __nv_bfloat162 a23 = __floats2bfloat162_rn(m2.z, m2.w);
    __nv_bfloat162 c01 = __floats2bfloat162_rn(b2.x, b2.y);
    __nv_bfloat162 c23 = __floats2bfloat162_rn(b2.z, b2.w);
    uint2 u1 = make_uint2(*(uint32_t*)&a01, *(uint32_t*)&a23);
    uint2 u2 = make_uint2(*(uint32_t*)&c01, *(uint32_t*)&c23);
    *(uint2*)(g_B1 + (size_t)bm * DD + t * 4) = u1;
    *(uint2*)(g_B2 + (size_t)bm * DD + t * 4) = u2;

    float mpx = mk.x * p.x, mpy = mk.y * p.y, mpz = mk.z * p.z, mpw = mk.w * p.w;
    float psum = mpx * mpx + mpy * mpy + mpz * mpz + mpw * mpw;

    __shared__ float red[256];
    red[t] = psum;
    __syncthreads();
    #pragma unroll
    for (int s = 128; s > 0; s >>= 1) {
        if (t < s) red[t] += red[t + s];
        __syncthreads();
    }
    if (t == 0) g_pterm[bm] = red[0];
}

// ---------------------------------------------------------------------------
// Helpers
// ---------------------------------------------------------------------------
__device__ __forceinline__ void cp_async16(void* smem_dst, const void* gmem_src) {
    uint32_t s = (uint32_t)__cvta_generic_to_shared(smem_dst);
    asm volatile("cp.async.cg.shared.global [%0], [%1], 16;\n" :: "r"(s), "l"(gmem_src));
}
__device__ __forceinline__ uint32_t sq_bf16x2(uint32_t x) {
    __nv_bfloat162 v = *reinterpret_cast<__nv_bfloat162*>(&x);
    __nv_bfloat162 r = __hmul2(v, v);
    return *reinterpret_cast<uint32_t*>(&r);
}

__device__ __forceinline__ void ldg_q(float4* qr, const float* qbase, int doff,
                                      int q_row0, int q_g) {
    #pragma unroll
    for (int p = 0; p < 8; p++)
        qr[p] = *(const float4*)(qbase + (size_t)(q_row0 + 16 * p) * DD + doff + q_g * 4);
}
__device__ __forceinline__ void sts_q(__nv_bfloat16* sQ, const float4* qr,
                                      int q_row0, int q_g) {
    #pragma unroll
    for (int p = 0; p < 8; p++) {
        int so = (q_row0 + 16 * p) * ASTRIDE + q_g * 4;
        __nv_bfloat162 lo = __floats2bfloat162_rn(qr[p].x, qr[p].y);
        __nv_bfloat162 hi = __floats2bfloat162_rn(qr[p].z, qr[p].w);
        uint2 v = make_uint2(*(uint32_t*)&lo, *(uint32_t*)&hi);
        *(uint2*)(&sQ[so]) = v;
    }
}
__device__ __forceinline__ void issue_B(__nv_bfloat16* dstStage,
                                        const __nv_bfloat16* B1base,
                                        const __nv_bfloat16* B2base,
                                        int doff, int t) {
    #pragma unroll
    for (int h = 0; h < 4; h++) {
        int idx = t + 256 * h;
        int mat = idx >> 9;
        int row = (idx >> 3) & 63;
        int g   = idx & 7;
        const __nv_bfloat16* src = (mat ? B2base : B1base) + (size_t)row * DD + doff + g * 8;
        cp_async16(dstStage + mat * BELEMS + row * ASTRIDE + g * 8, src);
    }
    asm volatile("cp.async.commit_group;\n");
}

__device__ __forceinline__ void compute_chunk(const __nv_bfloat16* sQ,
                                              const __nv_bfloat16* sB1,
                                              const __nv_bfloat16* sB2,
                                              float (&acc)[2][4][4],
                                              int wm, int wn, int gid, int tig) {
    #pragma unroll
    for (int kk = 0; kk < KC; kk += 16) {
        uint32_t aq[2][4], aq2[2][4];
        #pragma unroll
        for (int mt = 0; mt < 2; mt++) {
            int r = wm * 32 + mt * 16 + gid;
            const __nv_bfloat16* base = &sQ[r * ASTRIDE + kk + tig * 2];
            aq[mt][0] = *(const uint32_t*)(base);
            aq[mt][1] = *(const uint32_t*)(base + 8 * ASTRIDE);
            aq[mt][2] = *(const uint32_t*)(base + 8);
            aq[mt][3] = *(const uint32_t*)(base + 8 * ASTRIDE + 8);
            #pragma unroll
            for (int r4 = 0; r4 < 4; r4++) aq2[mt][r4] = sq_bf16x2(aq[mt][r4]);
        }
        uint32_t b1f[4][2], b2f[4][2];
        #pragma unroll
        for (int nt = 0; nt < 4; nt++) {
            int nn = wn * 32 + nt * 8 + gid;
            const __nv_bfloat16* p1 = &sB1[nn * ASTRIDE + kk + tig * 2];
            const __nv_bfloat16* p2 = &sB2[nn * ASTRIDE + kk + tig * 2];
            b1f[nt][0] = *(const uint32_t*)(p1);
            b1f[nt][1] = *(const uint32_t*)(p1 + 8);
            b2f[nt][0] = *(const uint32_t*)(p2);
            b2f[nt][1] = *(const uint32_t*)(p2 + 8);
        }
        #pragma unroll
        for (int mt = 0; mt < 2; mt++)
            #pragma unroll
            for (int nt = 0; nt < 4; nt++) {
                asm volatile(
                    "mma.sync.aligned.m16n8k16.row.col.f32.bf16.bf16.f32 "
                    "{%0,%1,%2,%3}, {%4,%5,%6,%7}, {%8,%9}, {%0,%1,%2,%3};\n"
                    : "+f"(acc[mt][nt][0]), "+f"(acc[mt][nt][1]),
                      "+f"(acc[mt][nt][2]), "+f"(acc[mt][nt][3])
                    : "r"(aq2[mt][0]), "r"(aq2[mt][1]),
                      "r"(aq2[mt][2]), "r"(aq2[mt][3]),
                      "r"(b1f[nt][0]), "r"(b1f[nt][1]));
                asm volatile(
                    "mma.sync.aligned.m16n8k16.row.col.f32.bf16.bf16.f32 "
                    "{%0,%1,%2,%3}, {%4,%5,%6,%7}, {%8,%9}, {%0,%1,%2,%3};\n"
                    : "+f"(acc[mt][nt][0]), "+f"(acc[mt][nt][1]),
                      "+f"(acc[mt][nt][2]), "+f"(acc[mt][nt][3])
                    : "r"(aq[mt][0]), "r"(aq[mt][1]),
                      "r"(aq[mt][2]), "r"(aq[mt][3]),
                      "r"(b2f[nt][0]), "r"(b2f[nt][1]));
            }
    }
}

// One pipeline iteration. QSEL/BSTG compile-time; I runtime chunk index.
// Ordering proof: single top barrier orders compute(i-2) reads vs cp.async(i)
// writes into stage (i+2)%4 (same buffer), and STS(i) vs compute(i) reads.
#define CHUNK_BODY(I, QSEL, BSTG, DO_ISSUE, IS_LAST)                          \
    {                                                                          \
        const int i_ = (I);                                                    \
        __nv_bfloat16* sQ_  = smem + (QSEL) * QELEMS;                          \
        __nv_bfloat16* sB1_ = smem + BBASE + (BSTG) * BSTAGE;                  \
        __nv_bfloat16* sB2_ = sB1_ + BELEMS;                                   \
        float4* qr_ = (QSEL) ? qr1 : qr0;                                      \
        sts_q(sQ_, qr_, q_row0, q_g);                                          \
        if (IS_LAST) asm volatile("cp.async.wait_group 0;\n");                 \
        else         asm volatile("cp.async.wait_group 1;\n");                 \
        __syncthreads();                                                       \
        if (DO_ISSUE) {                                                        \
            const int d2 = (i_ + 2) * KC;                                      \
            issue_B(smem + BBASE + (((BSTG) + 2) & 3) * BSTAGE,                \
                    B1base, B2base, d2, t);                                    \
            ldg_q(qr_, qbase, d2, q_row0, q_g);                                \
        }                                                                      \
        compute_chunk(sQ_, sB1_, sB2_, acc, wm, wn, gid, tig);                 \
    }

// ---------------------------------------------------------------------------
// Main kernel: distance-2 pipelined fused dual-GEMM.
// grid = (16, 8) = 128 CTAs; block = 256 (8 warps, 4x2), warp tile 32x32.
// ---------------------------------------------------------------------------
__global__ __launch_bounds__(NTHREADS, 1)
void proto_logits_kernel(const float* __restrict__ q,
                         const float* __restrict__ scale,
                         float* __restrict__ out) {
    extern __shared__ __align__(16) __nv_bfloat16 smem[];

    const int b    = blockIdx.y;
    const int n0   = blockIdx.x * NROWS;
    const int t    = threadIdx.x;
    const int warp = t >> 5;
    const int lane = t & 31;
    const int wm   = warp >> 1;     // 0..3
    const int wn   = warp & 1;      // 0..1
    const int gid  = lane >> 2;
    const int tig  = lane & 3;

    float acc[2][4][4];
    #pragma unroll
    for (int i = 0; i < 2; i++)
        #pragma unroll
        for (int j = 0; j < 4; j++)
            #pragma unroll
            for (int k = 0; k < 4; k++) acc[i][j][k] = 0.f;

    const float*         qbase  = q    + ((size_t)b * NQ + n0) * DD;
    const __nv_bfloat16* B1base = g_B1 + (size_t)b * MP * DD;
    const __nv_bfloat16* B2base = g_B2 + (size_t)b * MP * DD;

    const int q_row0 = t >> 4;          // rows: q_row0 + 16*p
    const int q_g    = t & 15;

    float4 qr0[8], qr1[8];

    // ---- prologue: B chunks 0,1 via cp.async (2 groups); q chunks 0,1 via LDG
    issue_B(smem + BBASE + 0 * BSTAGE, B1base, B2base, 0, t);
    issue_B(smem + BBASE + 1 * BSTAGE, B1base, B2base, KC, t);
    ldg_q(qr0, qbase, 0, q_row0, q_g);
    ldg_q(qr1, qbase, KC, q_row0, q_g);

    // ---- main loop: 12 iters unrolled x4, then 4 peeled
    for (int i0 = 0; i0 < 12; i0 += 4) {
        CHUNK_BODY(i0 + 0, 0, 0, true, false);
        CHUNK_BODY(i0 + 1, 1, 1, true, false);
        CHUNK_BODY(i0 + 2, 0, 2, true, false);
        CHUNK_BODY(i0 + 3, 1, 3, true, false);
    }
    CHUNK_BODY(12, 0, 0, true,  false);
    CHUNK_BODY(13, 1, 1, true,  false);
    CHUNK_BODY(14, 0, 2, false, false);
    CHUNK_BODY(15, 1, 3, false, true);

    // ---- epilogue: out = scale/D * (acc + pterm[col])
    const float s = scale[0] * (1.0f / (float)DD);
    float* obase = out + ((size_t)b * NQ + n0) * MP;
    const float* pt = g_pterm + b * MP;
    #pragma unroll
    for (int mt = 0; mt < 2; mt++) {
        #pragma unroll
        for (int nt = 0; nt < 4; nt++) {
            int r0 = wm * 32 + mt * 16 + gid;
            int c0 = wn * 32 + nt * 8 + tig * 2;
            float p0 = pt[c0];
            float p1 = pt[c0 + 1];
            float2 o01 = make_float2(s * (acc[mt][nt][0] + p0),
                                     s * (acc[mt][nt][1] + p1));
            float2 o23 = make_float2(s * (acc[mt][nt][2] + p0),
                                     s * (acc[mt][nt][3] + p1));
            *(float2*)(obase + (size_t)r0 * MP + c0)       = o01;
            *(float2*)(obase + (size_t)(r0 + 8) * MP + c0) = o23;
        }
    }
}

// ---------------------------------------------------------------------------
// Launch. Inputs: 0=prototypes, 1=masktypes, 2=query, 3=support,
// 4=support_labels, 5=scale. Output: [8,2048,64] f32.
// ---------------------------------------------------------------------------
extern "C" void kernel_launch(void* const* d_in, const int* in_sizes, int n_in,
                              void* d_out, int out_size) {
    const float* proto = (const float*)d_in[0];
    const float* mask  = (const float*)d_in[1];
    const float* query = (const float*)d_in[2];
    const float* scale = (const float*)d_in[5];
    float* out = (float*)d_out;

    cudaFuncSetAttribute(proto_logits_kernel,
                         cudaFuncAttributeMaxDynamicSharedMemorySize, SMEM_TOTAL);

    proto_prep_kernel<<<BS * MP, 256>>>(proto, mask);
    dim3 grid(NQ / NROWS, BS);
    proto_logits_kernel<<<grid, NTHREADS, SMEM_TOTAL>>>(query, scale, out);
}